// round 1
// baseline (speedup 1.0000x reference)
#include <cuda_runtime.h>
#include <math.h>

#define Bn 512
#define Tn 128
#define En 128
#define Hn 256
#define G4 1024
#define KTAGS 10

typedef unsigned long long ull;

// ---------------- scratch (static device globals; no allocation) ----------------
__device__ float g_hall[(size_t)Bn * Tn * 2 * Hn];   // [b][t][512] concat(fwd,bwd), 134 MB
__device__ float g_hstate[2][2][Bn][Hn];             // [ping][dir][b][h]
__device__ float g_c[2][Bn][Hn];                     // [dir][b][h], updated in place
__device__ int   g_len[Bn];

// ---------------- f32x2 packed helpers ----------------
__device__ __forceinline__ ull pk(float lo, float hi) {
    ull r; asm("mov.b64 %0, {%1, %2};" : "=l"(r) : "f"(lo), "f"(hi)); return r;
}
__device__ __forceinline__ void ffma2(ull& d, ull a, ull b) {
    asm("fma.rn.f32x2 %0, %1, %2, %0;" : "+l"(d) : "l"(a), "l"(b));
}
__device__ __forceinline__ float upk_lo(ull v) { return __uint_as_float((unsigned)(v & 0xffffffffULL)); }
__device__ __forceinline__ float upk_hi(ull v) { return __uint_as_float((unsigned)(v >> 32)); }

__device__ __forceinline__ float sigm(float x) { return 1.0f / (1.0f + expf(-x)); }

// ---------------- lengths ----------------
__global__ void lengths_kernel(const int* __restrict__ word, float* __restrict__ out_len) {
    int b = blockIdx.x * blockDim.x + threadIdx.x;
    if (b < Bn) {
        const int* w = word + (size_t)b * Tn;
        int c = 0;
        #pragma unroll 8
        for (int t = 0; t < Tn; t++) c += (w[t] != 0);
        g_len[b] = c;
        out_len[b] = (float)c;
    }
}

// ---------------- fused LSTM step: z = x_t@W + b + h_prev@U, then gates ----------------
// grid: (8 batch tiles of 64, 8 hidden chunks of 32, 2 directions), 256 threads.
// Output N=128 columns per CTA, interleaved layout n = jj_local*4 + gate so each
// thread holds full (i,f,g,o) for 2 hidden cells x 4 batch rows in registers.
__global__ void __launch_bounds__(256)
lstm_step(int s,
          const int* __restrict__ word,
          const float* __restrict__ emb,
          const float* __restrict__ Wf, const float* __restrict__ Uf, const float* __restrict__ bf,
          const float* __restrict__ Wb, const float* __restrict__ Ub, const float* __restrict__ bb)
{
    const int dir = blockIdx.z;
    const int t   = dir ? (Tn - 1 - s) : s;
    const int b0  = blockIdx.x * 64;
    const int j0  = blockIdx.y * 32;
    const float* W    = dir ? Wb : Wf;
    const float* U    = dir ? Ub : Uf;
    const float* bias = dir ? bb : bf;

    __shared__ float A_s[32][68];    // [k][m], stride 68 (16B aligned, low conflict)
    __shared__ float B_s[32][128];   // [k][n]
    __shared__ int   w_s[64];

    const int tid = threadIdx.x;
    const int ty = tid >> 4;         // 0..15 -> 4 M rows each
    const int tx = tid & 15;         // 0..15 -> 8 N cols each

    if (tid < 64) w_s[tid] = word[(size_t)(b0 + tid) * Tn + t];

    // acc[p][n]: p = M-pair (rows ty*4+2p, ty*4+2p+1), n = local col; init with bias
    ull acc[2][8];
    #pragma unroll
    for (int n = 0; n < 8; n++) {
        int nn = tx * 8 + n;
        int col = (nn & 3) * Hn + j0 + (nn >> 2);
        float bv = __ldg(&bias[col]);
        ull p = pk(bv, bv);
        acc[0][n] = p; acc[1][n] = p;
    }

    const int ping = s & 1;
    const float* hprev = &g_hstate[ping][dir][0][0];

    const int nchunks = (s == 0) ? 4 : 12;   // first 4 chunks: x@W (K=128); rest: h@U (K=256)
    __syncthreads();

    for (int kc = 0; kc < nchunks; kc++) {
        const int kbase = kc * 32;
        const bool ph1 = (kbase < 128);

        // load A tile [32k x 64m]: 2048 elems / 256 threads
        #pragma unroll
        for (int i = 0; i < 8; i++) {
            int idx = tid + 256 * i;
            int kl = idx & 31, m = idx >> 5;
            float v;
            if (ph1) v = __ldg(&emb[(size_t)w_s[m] * En + kbase + kl]);
            else     v = __ldg(&hprev[(size_t)(b0 + m) * Hn + (kbase - 128) + kl]);
            A_s[kl][m] = v;
        }
        // load B tile [32k x 128n] with permuted columns: 4096 elems / 256 threads
        const float* Bsrc = ph1 ? (W + (size_t)kbase * G4) : (U + (size_t)(kbase - 128) * G4);
        #pragma unroll
        for (int i = 0; i < 16; i++) {
            int idx = tid + 256 * i;
            int n = idx & 127, kl = idx >> 7;
            int col = (n & 3) * Hn + j0 + (n >> 2);
            B_s[kl][n] = __ldg(&Bsrc[(size_t)kl * G4 + col]);
        }
        __syncthreads();

        #pragma unroll
        for (int kl = 0; kl < 32; kl++) {
            float4 a4 = *(const float4*)&A_s[kl][ty * 4];
            ull A0 = pk(a4.x, a4.y);
            ull A1 = pk(a4.z, a4.w);
            float4 b4a = *(const float4*)&B_s[kl][tx * 8];
            float4 b4b = *(const float4*)&B_s[kl][tx * 8 + 4];
            float bv[8] = {b4a.x, b4a.y, b4a.z, b4a.w, b4b.x, b4b.y, b4b.z, b4b.w};
            #pragma unroll
            for (int n = 0; n < 8; n++) {
                ull bp = pk(bv[n], bv[n]);
                ffma2(acc[0][n], A0, bp);
                ffma2(acc[1][n], A1, bp);
            }
        }
        __syncthreads();
    }

    // ---- pointwise LSTM epilogue (all gates in registers) ----
    const int pingW = ping ^ 1;
    #pragma unroll
    for (int p = 0; p < 2; p++) {
        #pragma unroll
        for (int r = 0; r < 2; r++) {
            const int m = ty * 4 + p * 2 + r;
            const int b = b0 + m;
            #pragma unroll
            for (int c = 0; c < 2; c++) {
                const int jj = j0 + tx * 2 + c;
                float iv = r ? upk_hi(acc[p][c * 4 + 0]) : upk_lo(acc[p][c * 4 + 0]);
                float fv = r ? upk_hi(acc[p][c * 4 + 1]) : upk_lo(acc[p][c * 4 + 1]);
                float gv = r ? upk_hi(acc[p][c * 4 + 2]) : upk_lo(acc[p][c * 4 + 2]);
                float ov = r ? upk_hi(acc[p][c * 4 + 3]) : upk_lo(acc[p][c * 4 + 3]);
                float cp = (s == 0) ? 0.0f : g_c[dir][b][jj];
                float ii = sigm(iv);
                float ff = sigm(fv);
                float gg = tanhf(gv);
                float oo = sigm(ov);
                float cn = ff * cp + ii * gg;
                float hn = oo * tanhf(cn);
                g_c[dir][b][jj] = cn;
                g_hstate[pingW][dir][b][jj] = hn;
                g_hall[((size_t)b * Tn + t) * (2 * Hn) + dir * Hn + jj] = hn;
            }
        }
    }
}

// ---------------- dense + softmax: probs = softmax(h_all @ Wd + bd) ----------------
// one warp per (b,t) row; 8 warps per block.
__global__ void __launch_bounds__(256)
dense_softmax(const float* __restrict__ Wd, const float* __restrict__ bd, float* __restrict__ probs)
{
    __shared__ float wd_s[2 * Hn * KTAGS + KTAGS];
    const int tid = threadIdx.x;
    for (int i = tid; i < 2 * Hn * KTAGS; i += 256) wd_s[i] = Wd[i];
    if (tid < KTAGS) wd_s[2 * Hn * KTAGS + tid] = bd[tid];
    __syncthreads();

    const int warp = tid >> 5, lane = tid & 31;
    const size_t row = (size_t)blockIdx.x * 8 + warp;     // 0..65535
    const float* h = &g_hall[row * (2 * Hn)];

    float acc[KTAGS];
    #pragma unroll
    for (int k = 0; k < KTAGS; k++) acc[k] = 0.0f;

    #pragma unroll
    for (int q = 0; q < 16; q++) {
        int e = lane + 32 * q;
        float hv = h[e];
        #pragma unroll
        for (int k = 0; k < KTAGS; k++) acc[k] += hv * wd_s[e * KTAGS + k];
    }
    #pragma unroll
    for (int k = 0; k < KTAGS; k++) {
        #pragma unroll
        for (int off = 16; off > 0; off >>= 1)
            acc[k] += __shfl_xor_sync(0xffffffffu, acc[k], off);
        acc[k] += wd_s[2 * Hn * KTAGS + k];
    }
    float mx = acc[0];
    #pragma unroll
    for (int k = 1; k < KTAGS; k++) mx = fmaxf(mx, acc[k]);
    float den = 0.0f;
    #pragma unroll
    for (int k = 0; k < KTAGS; k++) den += expf(acc[k] - mx);
    float inv = 1.0f / den;
    #pragma unroll
    for (int k = 0; k < KTAGS; k++) {
        float pv = expf(acc[k] - mx) * inv;
        if (lane == k) probs[row * KTAGS + k] = pv;
    }
}

// ---------------- CRF log-likelihood: one warp per batch row ----------------
__global__ void crf_kernel(const int* __restrict__ label,
                           const float* __restrict__ trans,
                           const float* __restrict__ probs,
                           float* __restrict__ out_ll)
{
    const int b = blockIdx.x;
    const int lane = threadIdx.x;
    const int len = g_len[b];
    const float* P = probs + (size_t)b * Tn * KTAGS;
    const int* tg = label + (size_t)b * Tn;

    // unary
    float u = 0.0f;
    for (int t = lane; t < Tn; t += 32)
        if (t < len) u += P[t * KTAGS + tg[t]];
    // binary
    float bi = 0.0f;
    for (int t = lane; t < Tn - 1; t += 32)
        if (t < len - 1) bi += trans[tg[t] * KTAGS + tg[t + 1]];
    #pragma unroll
    for (int off = 16; off > 0; off >>= 1) {
        u  += __shfl_xor_sync(0xffffffffu, u, off);
        bi += __shfl_xor_sync(0xffffffffu, bi, off);
    }

    // forward algorithm: lane k (k<10) owns alpha_k
    const int kk = (lane < KTAGS) ? lane : 0;
    float tr[KTAGS];
    #pragma unroll
    for (int j = 0; j < KTAGS; j++) tr[j] = trans[j * KTAGS + kk];

    float alpha = (lane < KTAGS) ? P[kk] : -1e30f;
    for (int t = 1; t < Tn; t++) {
        float aj[KTAGS];
        #pragma unroll
        for (int j = 0; j < KTAGS; j++) aj[j] = __shfl_sync(0xffffffffu, alpha, j);
        float m = -1e30f;
        #pragma unroll
        for (int j = 0; j < KTAGS; j++) m = fmaxf(m, aj[j] + tr[j]);
        float sum = 0.0f;
        #pragma unroll
        for (int j = 0; j < KTAGS; j++) sum += expf(aj[j] + tr[j] - m);
        float nv = m + logf(sum) + P[t * KTAGS + kk];
        if (t < len && lane < KTAGS) alpha = nv;
    }
    float aj[KTAGS];
    #pragma unroll
    for (int j = 0; j < KTAGS; j++) aj[j] = __shfl_sync(0xffffffffu, alpha, j);
    float m = -1e30f;
    #pragma unroll
    for (int j = 0; j < KTAGS; j++) m = fmaxf(m, aj[j]);
    float sum = 0.0f;
    #pragma unroll
    for (int j = 0; j < KTAGS; j++) sum += expf(aj[j] - m);
    float ln = (len == 0) ? 0.0f : (m + logf(sum));

    if (lane == 0) out_ll[b] = u + bi - ln;
}

// ---------------- launch ----------------
extern "C" void kernel_launch(void* const* d_in, const int* in_sizes, int n_in,
                              void* d_out, int out_size)
{
    const int*   word  = (const int*)d_in[0];
    const int*   label = (const int*)d_in[1];
    const float* emb   = (const float*)d_in[2];
    const float* Wf    = (const float*)d_in[3];
    const float* Uf    = (const float*)d_in[4];
    const float* bf    = (const float*)d_in[5];
    const float* Wb    = (const float*)d_in[6];
    const float* Ub    = (const float*)d_in[7];
    const float* bb    = (const float*)d_in[8];
    const float* Wd    = (const float*)d_in[9];
    const float* bd    = (const float*)d_in[10];
    const float* trans = (const float*)d_in[11];

    float* out      = (float*)d_out;
    float* probs    = out;                                 // 512*128*10
    float* out_len  = out + (size_t)Bn * Tn * KTAGS;       // 512
    float* out_ll   = out_len + Bn;                        // 512

    lengths_kernel<<<2, 256>>>(word, out_len);

    dim3 grid(8, 8, 2);
    for (int s = 0; s < Tn; s++)
        lstm_step<<<grid, 256>>>(s, word, emb, Wf, Uf, bf, Wb, Ub, bb);

    dense_softmax<<<8192, 256>>>(Wd, bd, probs);
    crf_kernel<<<Bn, 32>>>(label, trans, probs, out_ll);
}

// round 2
// speedup vs baseline: 1.5328x; 1.5328x over previous
#include <cuda_runtime.h>
#include <math.h>

#define Bn 512
#define Tn 128
#define En 128
#define Hn 256
#define G4 1024
#define KTAGS 10

typedef unsigned long long ull;

// ---------------- scratch (static device globals; no allocation) ----------------
__device__ float g_hall[(size_t)Bn * Tn * 2 * Hn];   // [b][t][512] concat(fwd,bwd)
__device__ float g_hstate[2][2][Bn][Hn];             // [ping][dir][b][h]
__device__ float g_c[2][Bn][Hn];                     // [dir][b][h]
__device__ int   g_len[Bn];

// ---------------- f32x2 packed helpers ----------------
__device__ __forceinline__ ull pk(float lo, float hi) {
    ull r; asm("mov.b64 %0, {%1, %2};" : "=l"(r) : "f"(lo), "f"(hi)); return r;
}
__device__ __forceinline__ void ffma2(ull& d, ull a, ull b) {
    asm("fma.rn.f32x2 %0, %1, %2, %0;" : "+l"(d) : "l"(a), "l"(b));
}
__device__ __forceinline__ float upk_lo(ull v) { return __uint_as_float((unsigned)(v & 0xffffffffULL)); }
__device__ __forceinline__ float upk_hi(ull v) { return __uint_as_float((unsigned)(v >> 32)); }

__device__ __forceinline__ float sigm(float x) { return 1.0f / (1.0f + expf(-x)); }

// ---------------- lengths ----------------
__global__ void lengths_kernel(const int* __restrict__ word, float* __restrict__ out_len) {
    int b = blockIdx.x * blockDim.x + threadIdx.x;
    if (b < Bn) {
        const int* w = word + (size_t)b * Tn;
        int c = 0;
        #pragma unroll 8
        for (int t = 0; t < Tn; t++) c += (w[t] != 0);
        g_len[b] = c;
        out_len[b] = (float)c;
    }
}

// ---------------- fused LSTM step ----------------
// grid (8 batch tiles x 8 cell chunks x 2 dirs) = 128 CTAs, 256 threads.
// Tile: 64 batch rows x 32 hidden cells (=128 gate columns, permuted n = cell*4+gate).
// A stored in SMEM pre-duplicated as f32x2 pairs; acc pairs along N (gates).
struct StepSmem {
    ull   A[2][32][66];     // [buf][k][m] duplicated (a,a); row 66 -> 16B aligned, low conflict
    float B[2][32][128];    // [buf][k][n] permuted gate columns
    int   w[64];
};

__global__ void __launch_bounds__(256)
lstm_step(int s,
          const int* __restrict__ word,
          const float* __restrict__ emb,
          const float* __restrict__ Wf, const float* __restrict__ Uf, const float* __restrict__ bf,
          const float* __restrict__ Wb, const float* __restrict__ Ub, const float* __restrict__ bb)
{
    extern __shared__ char smem_raw[];
    StepSmem* S = (StepSmem*)smem_raw;

    const int dir = blockIdx.z;
    const int t   = dir ? (Tn - 1 - s) : s;
    const int b0  = blockIdx.x * 64;
    const int j0  = blockIdx.y * 32;
    const float* W    = dir ? Wb : Wf;
    const float* U    = dir ? Ub : Uf;
    const float* bias = dir ? bb : bf;

    const int tid = threadIdx.x;
    const int ty = tid >> 4;     // 0..15 -> rows ty*4..ty*4+3
    const int tx = tid & 15;     // 0..15 -> cells j0+tx and j0+16+tx

    if (tid < 64) S->w[tid] = word[(size_t)(b0 + tid) * Tn + t];
    __syncthreads();

    // acc[r][c][p]: r = local row 0..3, c = cell half, p = gate pair ((i,f),(g,o))
    ull acc[4][2][2];
    #pragma unroll
    for (int c = 0; c < 2; c++) {
        int jj = j0 + tx + 16 * c;
        ull p0 = pk(__ldg(&bias[jj]),          __ldg(&bias[Hn + jj]));
        ull p1 = pk(__ldg(&bias[2 * Hn + jj]), __ldg(&bias[3 * Hn + jj]));
        #pragma unroll
        for (int r = 0; r < 4; r++) { acc[r][c][0] = p0; acc[r][c][1] = p1; }
    }

    const int ping = s & 1;
    const float* hprev = &g_hstate[ping][dir][0][0];
    const int nch = (s == 0) ? 4 : 12;

    float ra[8], rb[16];

    // ---- register prefetch helpers ----
    auto rload = [&](int kc) {
        const int kb = kc * 32;
        if (kb < 128) {
            #pragma unroll
            for (int i = 0; i < 8; i++) {
                int idx = tid + 256 * i; int kl = idx & 31, m = idx >> 5;
                ra[i] = __ldg(&emb[(size_t)S->w[m] * En + kb + kl]);
            }
        } else {
            #pragma unroll
            for (int i = 0; i < 8; i++) {
                int idx = tid + 256 * i; int kl = idx & 31, m = idx >> 5;
                ra[i] = __ldg(&hprev[(size_t)(b0 + m) * Hn + (kb - 128) + kl]);
            }
        }
        const float* Bsrc = (kb < 128) ? (W + (size_t)kb * G4) : (U + (size_t)(kb - 128) * G4);
        #pragma unroll
        for (int i = 0; i < 16; i++) {
            int idx = tid + 256 * i; int n = idx & 127, kl = idx >> 7;
            int col = (n & 3) * Hn + j0 + (n >> 2);
            rb[i] = __ldg(&Bsrc[(size_t)kl * G4 + col]);
        }
    };
    auto rstore = [&](int buf) {
        #pragma unroll
        for (int i = 0; i < 8; i++) {
            int idx = tid + 256 * i; int kl = idx & 31, m = idx >> 5;
            S->A[buf][kl][m] = pk(ra[i], ra[i]);
        }
        #pragma unroll
        for (int i = 0; i < 16; i++) {
            int idx = tid + 256 * i; int n = idx & 127, kl = idx >> 7;
            S->B[buf][kl][n] = rb[i];
        }
    };

    rload(0); rstore(0);
    __syncthreads();

    for (int kc = 0; kc < nch; kc++) {
        if (kc + 1 < nch) rload(kc + 1);
        const int buf = kc & 1;

        #pragma unroll 8
        for (int kl = 0; kl < 32; kl++) {
            ulonglong2 a01 = *(const ulonglong2*)&S->A[buf][kl][ty * 4];
            ulonglong2 a23 = *(const ulonglong2*)&S->A[buf][kl][ty * 4 + 2];
            ulonglong2 b0v = *(const ulonglong2*)&S->B[buf][kl][tx * 4];
            ulonglong2 b1v = *(const ulonglong2*)&S->B[buf][kl][64 + tx * 4];
            ull ar[4] = {a01.x, a01.y, a23.x, a23.y};
            #pragma unroll
            for (int r = 0; r < 4; r++) {
                ffma2(acc[r][0][0], ar[r], b0v.x);
                ffma2(acc[r][0][1], ar[r], b0v.y);
                ffma2(acc[r][1][0], ar[r], b1v.x);
                ffma2(acc[r][1][1], ar[r], b1v.y);
            }
        }
        if (kc + 1 < nch) rstore(buf ^ 1);
        __syncthreads();
    }

    // ---- pointwise LSTM epilogue (register-resident gates) ----
    const int pingW = ping ^ 1;
    #pragma unroll
    for (int r = 0; r < 4; r++) {
        const int b = b0 + ty * 4 + r;
        #pragma unroll
        for (int c = 0; c < 2; c++) {
            const int jj = j0 + tx + 16 * c;
            float iv = upk_lo(acc[r][c][0]), fv = upk_hi(acc[r][c][0]);
            float gv = upk_lo(acc[r][c][1]), ov = upk_hi(acc[r][c][1]);
            float cp = (s == 0) ? 0.0f : g_c[dir][b][jj];
            float ii = sigm(iv);
            float ff = sigm(fv);
            float gg = tanhf(gv);
            float oo = sigm(ov);
            float cn = ff * cp + ii * gg;
            float hn = oo * tanhf(cn);
            g_c[dir][b][jj] = cn;
            g_hstate[pingW][dir][b][jj] = hn;
            g_hall[((size_t)b * Tn + t) * (2 * Hn) + dir * Hn + jj] = hn;
        }
    }
}

// ---------------- dense + softmax ----------------
__global__ void __launch_bounds__(256)
dense_softmax(const float* __restrict__ Wd, const float* __restrict__ bd, float* __restrict__ probs)
{
    __shared__ float wd_s[KTAGS][2 * Hn];   // transposed: conflict-free
    __shared__ float bd_s[KTAGS];
    const int tid = threadIdx.x;
    for (int i = tid; i < 2 * Hn * KTAGS; i += 256) {
        int e = i / KTAGS, k = i % KTAGS;
        wd_s[k][e] = Wd[i];
    }
    if (tid < KTAGS) bd_s[tid] = bd[tid];
    __syncthreads();

    const int warp = tid >> 5, lane = tid & 31;
    const size_t row = (size_t)blockIdx.x * 8 + warp;
    const float* h = &g_hall[row * (2 * Hn)];

    float acc[KTAGS];
    #pragma unroll
    for (int k = 0; k < KTAGS; k++) acc[k] = 0.0f;

    #pragma unroll
    for (int q = 0; q < 16; q++) {
        int e = lane + 32 * q;
        float hv = h[e];
        #pragma unroll
        for (int k = 0; k < KTAGS; k++) acc[k] += hv * wd_s[k][e];
    }
    #pragma unroll
    for (int k = 0; k < KTAGS; k++) {
        #pragma unroll
        for (int off = 16; off > 0; off >>= 1)
            acc[k] += __shfl_xor_sync(0xffffffffu, acc[k], off);
        acc[k] += bd_s[k];
    }
    float mx = acc[0];
    #pragma unroll
    for (int k = 1; k < KTAGS; k++) mx = fmaxf(mx, acc[k]);
    float den = 0.0f;
    #pragma unroll
    for (int k = 0; k < KTAGS; k++) den += expf(acc[k] - mx);
    float inv = 1.0f / den;
    #pragma unroll
    for (int k = 0; k < KTAGS; k++) {
        float pv = expf(acc[k] - mx) * inv;
        if (lane == k) probs[row * KTAGS + k] = pv;
    }
}

// ---------------- CRF log-likelihood ----------------
__global__ void crf_kernel(const int* __restrict__ label,
                           const float* __restrict__ trans,
                           const float* __restrict__ probs,
                           float* __restrict__ out_ll)
{
    const int b = blockIdx.x;
    const int lane = threadIdx.x;
    const int len = g_len[b];
    const float* P = probs + (size_t)b * Tn * KTAGS;
    const int* tg = label + (size_t)b * Tn;

    float u = 0.0f;
    for (int t = lane; t < Tn; t += 32)
        if (t < len) u += P[t * KTAGS + tg[t]];
    float bi = 0.0f;
    for (int t = lane; t < Tn - 1; t += 32)
        if (t < len - 1) bi += trans[tg[t] * KTAGS + tg[t + 1]];
    #pragma unroll
    for (int off = 16; off > 0; off >>= 1) {
        u  += __shfl_xor_sync(0xffffffffu, u, off);
        bi += __shfl_xor_sync(0xffffffffu, bi, off);
    }

    const int kk = (lane < KTAGS) ? lane : 0;
    float tr[KTAGS];
    #pragma unroll
    for (int j = 0; j < KTAGS; j++) tr[j] = trans[j * KTAGS + kk];

    float alpha = (lane < KTAGS) ? P[kk] : -1e30f;
    for (int t = 1; t < Tn; t++) {
        float aj[KTAGS];
        #pragma unroll
        for (int j = 0; j < KTAGS; j++) aj[j] = __shfl_sync(0xffffffffu, alpha, j);
        float m = -1e30f;
        #pragma unroll
        for (int j = 0; j < KTAGS; j++) m = fmaxf(m, aj[j] + tr[j]);
        float sum = 0.0f;
        #pragma unroll
        for (int j = 0; j < KTAGS; j++) sum += expf(aj[j] + tr[j] - m);
        float nv = m + logf(sum) + P[t * KTAGS + kk];
        if (t < len && lane < KTAGS) alpha = nv;
    }
    float aj[KTAGS];
    #pragma unroll
    for (int j = 0; j < KTAGS; j++) aj[j] = __shfl_sync(0xffffffffu, alpha, j);
    float m = -1e30f;
    #pragma unroll
    for (int j = 0; j < KTAGS; j++) m = fmaxf(m, aj[j]);
    float sum = 0.0f;
    #pragma unroll
    for (int j = 0; j < KTAGS; j++) sum += expf(aj[j] - m);
    float ln = (len == 0) ? 0.0f : (m + logf(sum));

    if (lane == 0) out_ll[b] = u + bi - ln;
}

// ---------------- launch ----------------
extern "C" void kernel_launch(void* const* d_in, const int* in_sizes, int n_in,
                              void* d_out, int out_size)
{
    const int*   word  = (const int*)d_in[0];
    const int*   label = (const int*)d_in[1];
    const float* emb   = (const float*)d_in[2];
    const float* Wf    = (const float*)d_in[3];
    const float* Uf    = (const float*)d_in[4];
    const float* bf    = (const float*)d_in[5];
    const float* Wb    = (const float*)d_in[6];
    const float* Ub    = (const float*)d_in[7];
    const float* bb    = (const float*)d_in[8];
    const float* Wd    = (const float*)d_in[9];
    const float* bd    = (const float*)d_in[10];
    const float* trans = (const float*)d_in[11];

    float* out      = (float*)d_out;
    float* probs    = out;                                 // 512*128*10
    float* out_len  = out + (size_t)Bn * Tn * KTAGS;       // 512
    float* out_ll   = out_len + Bn;                        // 512

    const int smem_bytes = (int)sizeof(StepSmem);
    cudaFuncSetAttribute(lstm_step, cudaFuncAttributeMaxDynamicSharedMemorySize, smem_bytes);

    lengths_kernel<<<2, 256>>>(word, out_len);

    dim3 grid(8, 8, 2);
    for (int s = 0; s < Tn; s++)
        lstm_step<<<grid, 256, smem_bytes>>>(s, word, emb, Wf, Uf, bf, Wb, Ub, bb);

    dense_softmax<<<8192, 256>>>(Wd, bd, probs);
    crf_kernel<<<Bn, 32>>>(label, trans, probs, out_ll);
}